// round 1
// baseline (speedup 1.0000x reference)
#include <cuda_runtime.h>
#include <cuda_bf16.h>
#include <cstdint>

// ---------------- problem dims ----------------
#define NTOK 4096      // B*S
#define EDIM 1024
#define CDIM 1024
#define HDIM 4096
#define VDIM 32000
#define LN_EPS 1e-5f

// ---------------- GEMM tiling ----------------
#define BM 128
#define BN 128
#define BK 32
#define LDA 40    // BK + 8 halfs (pad)
#define LDB 136   // BN + 8 halfs (pad)
#define A_TILE (BM * LDA)   // 5120 halfs
#define B_TILE (BK * LDB)   // 4352 halfs
#define SMEM_BYTES ((4 * A_TILE + 4 * B_TILE) * 2)   // 75776 B (hi+lo, double buffered)

// ---------------- scratch (no allocations allowed) ----------------
__device__ float g_x  [NTOK * EDIM];
__device__ float g_xc [NTOK * (EDIM + CDIM)];
__device__ float g_h1 [NTOK * HDIM];
__device__ float g_h  [NTOK * HDIM];
__device__ float g_del[NTOK * CDIM];
__device__ float g_fg [NTOK * CDIM];
__device__ float g_ig [NTOK * CDIM];
__device__ float g_ctx[NTOK * CDIM];

// ---------------- small helpers ----------------
__device__ __forceinline__ uint32_t smem_u32(const void* p) {
    return (uint32_t)__cvta_generic_to_shared(p);
}

__device__ __forceinline__ void ldmA(uint32_t* r, uint32_t addr) {
    asm volatile("ldmatrix.sync.aligned.m8n8.x4.shared.b16 {%0,%1,%2,%3}, [%4];"
                 : "=r"(r[0]), "=r"(r[1]), "=r"(r[2]), "=r"(r[3]) : "r"(addr));
}
__device__ __forceinline__ void ldmB(uint32_t* r, uint32_t addr) {
    asm volatile("ldmatrix.sync.aligned.m8n8.x2.trans.shared.b16 {%0,%1}, [%2];"
                 : "=r"(r[0]), "=r"(r[1]) : "r"(addr));
}
__device__ __forceinline__ void mma_bf16(float* d, const uint32_t* a, const uint32_t* b) {
    asm volatile("mma.sync.aligned.m16n8k16.row.col.f32.bf16.bf16.f32 "
                 "{%0,%1,%2,%3}, {%4,%5,%6,%7}, {%8,%9}, {%0,%1,%2,%3};"
                 : "+f"(d[0]), "+f"(d[1]), "+f"(d[2]), "+f"(d[3])
                 : "r"(a[0]), "r"(a[1]), "r"(a[2]), "r"(a[3]), "r"(b[0]), "r"(b[1]));
}

// split fp32 pair into packed bf16 hi and bf16 lo residual
__device__ __forceinline__ void cvt2(float x, float y, uint32_t& hi, uint32_t& lo) {
    __nv_bfloat16 hx = __float2bfloat16(x);
    __nv_bfloat16 hy = __float2bfloat16(y);
    __nv_bfloat16 lx = __float2bfloat16(x - __bfloat162float(hx));
    __nv_bfloat16 ly = __float2bfloat16(y - __bfloat162float(hy));
    __nv_bfloat162 H = __halves2bfloat162(hx, hy);
    __nv_bfloat162 L = __halves2bfloat162(lx, ly);
    hi = *reinterpret_cast<uint32_t*>(&H);
    lo = *reinterpret_cast<uint32_t*>(&L);
}

template <int ACT>
__device__ __forceinline__ float actf(float x) {
    if (ACT == 1) return fmaxf(x, 0.0f);
    if (ACT == 2) return tanhf(x);
    if (ACT == 3) return 1.0f / (1.0f + expf(-x));
    return x;
}

// ---------------- GEMM: C[M,N] = act(A[M,K] @ B[K,N] + bias) ----------------
// bf16x3 split emulation for fp32 accuracy. All dims divisible by tiles.
template <int ACT>
__global__ void __launch_bounds__(256, 1)
gemm3_kernel(const float* __restrict__ A, const float* __restrict__ Bw,
             const float* __restrict__ bias, float* __restrict__ C,
             int M, int N, int K)
{
    extern __shared__ __nv_bfloat16 smem[];
    __nv_bfloat16* sAhi = smem;
    __nv_bfloat16* sAlo = smem + 2 * A_TILE;
    __nv_bfloat16* sBhi = smem + 4 * A_TILE;
    __nv_bfloat16* sBlo = smem + 4 * A_TILE + 2 * B_TILE;

    const int t    = threadIdx.x;
    const int lane = t & 31;
    const int warp = t >> 5;
    const int wm   = warp >> 2;   // 0..1  -> 64-row slab
    const int wn   = warp & 3;    // 0..3  -> 32-col slab
    const int bm   = blockIdx.y * BM;
    const int bn   = blockIdx.x * BN;

    // gmem staging: each thread moves 16 A floats + 16 B floats per BK tile
    const int arow = t >> 1;          // 0..127
    const int acol = (t & 1) << 4;    // 0 | 16
    const int brow = t >> 3;          // 0..31
    const int bcol = (t & 7) << 4;    // 0..112

    const float* gA = A  + (size_t)(bm + arow) * K + acol;
    const float* gB = Bw + (size_t)brow * N + (bn + bcol);

    float acc[4][4][4];
#pragma unroll
    for (int a = 0; a < 4; a++)
#pragma unroll
        for (int b = 0; b < 4; b++)
#pragma unroll
            for (int c = 0; c < 4; c++) acc[a][b][c] = 0.0f;

    float4 ra[4], rb[4];
#pragma unroll
    for (int j = 0; j < 4; j++) ra[j] = *(const float4*)(gA + 4 * j);
#pragma unroll
    for (int j = 0; j < 4; j++) rb[j] = *(const float4*)(gB + 4 * j);

    // STS tile 0 into buffer 0
    {
        __nv_bfloat16* ah = sAhi; __nv_bfloat16* al = sAlo;
        __nv_bfloat16* bh = sBhi; __nv_bfloat16* bl = sBlo;
#pragma unroll
        for (int j = 0; j < 4; j++) {
            uint32_t h0, l0, h1, l1;
            cvt2(ra[j].x, ra[j].y, h0, l0);
            cvt2(ra[j].z, ra[j].w, h1, l1);
            int off = arow * LDA + acol + j * 4;
            *(uint32_t*)(ah + off)     = h0; *(uint32_t*)(ah + off + 2) = h1;
            *(uint32_t*)(al + off)     = l0; *(uint32_t*)(al + off + 2) = l1;
        }
#pragma unroll
        for (int j = 0; j < 4; j++) {
            uint32_t h0, l0, h1, l1;
            cvt2(rb[j].x, rb[j].y, h0, l0);
            cvt2(rb[j].z, rb[j].w, h1, l1);
            int off = brow * LDB + bcol + j * 4;
            *(uint32_t*)(bh + off)     = h0; *(uint32_t*)(bh + off + 2) = h1;
            *(uint32_t*)(bl + off)     = l0; *(uint32_t*)(bl + off + 2) = l1;
        }
    }
    __syncthreads();

    const int nk = K / BK;
    for (int it = 0; it < nk; ++it) {
        const int cur = it & 1;
        const bool has_next = (it + 1 < nk);
        if (has_next) {
            const float* pA = gA + (size_t)(it + 1) * BK;
            const float* pB = gB + (size_t)(it + 1) * BK * N;
#pragma unroll
            for (int j = 0; j < 4; j++) ra[j] = *(const float4*)(pA + 4 * j);
#pragma unroll
            for (int j = 0; j < 4; j++) rb[j] = *(const float4*)(pB + 4 * j);
        }

        const uint32_t aHi = smem_u32(sAhi + cur * A_TILE);
        const uint32_t aLo = smem_u32(sAlo + cur * A_TILE);
        const uint32_t bHi = smem_u32(sBhi + cur * B_TILE);
        const uint32_t bLo = smem_u32(sBlo + cur * B_TILE);

#pragma unroll
        for (int ks = 0; ks < 2; ++ks) {
            uint32_t fAh[4][4], fAl[4][4], fBh[4][2], fBl[4][2];
            const int mbase = wm * 64 + (lane & 15);
            const int koffA = ks * 16 + ((lane >> 4) << 3);
#pragma unroll
            for (int mt = 0; mt < 4; ++mt) {
                uint32_t off = (uint32_t)((mbase + mt * 16) * LDA + koffA) * 2;
                ldmA(fAh[mt], aHi + off);
                ldmA(fAl[mt], aLo + off);
            }
            const int krow = ks * 16 + (lane & 15);
#pragma unroll
            for (int nt = 0; nt < 4; ++nt) {
                uint32_t off = (uint32_t)(krow * LDB + wn * 32 + nt * 8) * 2;
                ldmB(fBh[nt], bHi + off);
                ldmB(fBl[nt], bLo + off);
            }
#pragma unroll
            for (int mt = 0; mt < 4; ++mt)
#pragma unroll
                for (int nt = 0; nt < 4; ++nt) {
                    mma_bf16(acc[mt][nt], fAh[mt], fBh[nt]);  // hi*hi
                    mma_bf16(acc[mt][nt], fAh[mt], fBl[nt]);  // hi*lo
                    mma_bf16(acc[mt][nt], fAl[mt], fBh[nt]);  // lo*hi
                }
        }

        if (has_next) {
            const int nxt = cur ^ 1;
            __nv_bfloat16* ah = sAhi + nxt * A_TILE; __nv_bfloat16* al = sAlo + nxt * A_TILE;
            __nv_bfloat16* bh = sBhi + nxt * B_TILE; __nv_bfloat16* bl = sBlo + nxt * B_TILE;
#pragma unroll
            for (int j = 0; j < 4; j++) {
                uint32_t h0, l0, h1, l1;
                cvt2(ra[j].x, ra[j].y, h0, l0);
                cvt2(ra[j].z, ra[j].w, h1, l1);
                int off = arow * LDA + acol + j * 4;
                *(uint32_t*)(ah + off)     = h0; *(uint32_t*)(ah + off + 2) = h1;
                *(uint32_t*)(al + off)     = l0; *(uint32_t*)(al + off + 2) = l1;
            }
#pragma unroll
            for (int j = 0; j < 4; j++) {
                uint32_t h0, l0, h1, l1;
                cvt2(rb[j].x, rb[j].y, h0, l0);
                cvt2(rb[j].z, rb[j].w, h1, l1);
                int off = brow * LDB + bcol + j * 4;
                *(uint32_t*)(bh + off)     = h0; *(uint32_t*)(bh + off + 2) = h1;
                *(uint32_t*)(bl + off)     = l0; *(uint32_t*)(bl + off + 2) = l1;
            }
            __syncthreads();
        }
    }

    // epilogue: bias + activation, fp32 stores
    const int r  = lane >> 2;
    const int cp = (lane & 3) * 2;
#pragma unroll
    for (int mt = 0; mt < 4; ++mt) {
#pragma unroll
        for (int nt = 0; nt < 4; ++nt) {
            const int row = bm + wm * 64 + mt * 16 + r;
            const int col = bn + wn * 32 + nt * 8 + cp;
            const float b0 = __ldg(bias + col);
            const float b1 = __ldg(bias + col + 1);
            float2 o0, o1;
            o0.x = actf<ACT>(acc[mt][nt][0] + b0);
            o0.y = actf<ACT>(acc[mt][nt][1] + b1);
            o1.x = actf<ACT>(acc[mt][nt][2] + b0);
            o1.y = actf<ACT>(acc[mt][nt][3] + b1);
            *(float2*)(C + (size_t)row * N + col)       = o0;
            *(float2*)(C + (size_t)(row + 8) * N + col) = o1;
        }
    }
}

// ---------------- block reduction (256 threads) ----------------
__device__ __forceinline__ float block_sum(float v, float* sbuf) {
    const int lane = threadIdx.x & 31;
    const int wid  = threadIdx.x >> 5;
#pragma unroll
    for (int o = 16; o; o >>= 1) v += __shfl_xor_sync(0xffffffffu, v, o);
    if (lane == 0) sbuf[wid] = v;
    __syncthreads();
    if (threadIdx.x < 32) {
        float r = (threadIdx.x < 8) ? sbuf[threadIdx.x] : 0.0f;
#pragma unroll
        for (int o = 4; o; o >>= 1) r += __shfl_xor_sync(0xffffffffu, r, o);
        if (threadIdx.x == 0) sbuf[8] = r;
    }
    __syncthreads();
    return sbuf[8];
}

// ---------------- embed + layernorm ----------------
__global__ void __launch_bounds__(256)
embed_ln_kernel(const int* __restrict__ ids, const float* __restrict__ table,
                const float* __restrict__ g, const float* __restrict__ b,
                float* __restrict__ out)
{
    __shared__ float sbuf[16];
    const int row = blockIdx.x;
    const int t = threadIdx.x;
    const float* e = table + (size_t)ids[row] * EDIM;
    float v[4];
    float s = 0.0f, s2 = 0.0f;
#pragma unroll
    for (int j = 0; j < 4; j++) {
        v[j] = e[t + j * 256];
        s += v[j]; s2 += v[j] * v[j];
    }
    const float S  = block_sum(s, sbuf);
    const float S2 = block_sum(s2, sbuf);
    const float mean = S * (1.0f / EDIM);
    const float var  = S2 * (1.0f / EDIM) - mean * mean;
    const float rs   = rsqrtf(var + LN_EPS);
#pragma unroll
    for (int j = 0; j < 4; j++) {
        const int c = t + j * 256;
        out[(size_t)row * EDIM + c] = (v[j] - mean) * rs * g[c] + b[c];
    }
}

// ---------------- concat [x | ctx] ----------------
__global__ void __launch_bounds__(256)
concat_kernel(const float* __restrict__ x, const float* __restrict__ ctx,
              float* __restrict__ xc, int first)
{
    const int gid = blockIdx.x * 256 + threadIdx.x;  // float4 index over [4096, 2048]
    const int row = gid >> 9;        // 512 float4 per row
    const int c4  = gid & 511;
    float4 v;
    if (c4 < 256) {
        v = ((const float4*)x)[(size_t)row * 256 + c4];
    } else if (first) {
        v = make_float4(0.0f, 0.0f, 0.0f, 0.0f);
    } else {
        v = ((const float4*)ctx)[(size_t)row * 256 + (c4 - 256)];
    }
    ((float4*)xc)[gid] = v;
}

// ---------------- gated ctx update + layernorm ----------------
__global__ void __launch_bounds__(256)
gate_ln_kernel(const float* __restrict__ f, const float* __restrict__ i,
               const float* __restrict__ d, float* __restrict__ ctx,
               const float* __restrict__ g, const float* __restrict__ b, int first)
{
    __shared__ float sbuf[16];
    const int row = blockIdx.x;
    const int t = threadIdx.x;
    float v[4];
    float s = 0.0f, s2 = 0.0f;
#pragma unroll
    for (int j = 0; j < 4; j++) {
        const size_t idx = (size_t)row * CDIM + t + j * 256;
        const float cv = first ? 0.0f : ctx[idx];
        v[j] = f[idx] * cv + i[idx] * d[idx];
        s += v[j]; s2 += v[j] * v[j];
    }
    const float S  = block_sum(s, sbuf);
    const float S2 = block_sum(s2, sbuf);
    const float mean = S * (1.0f / CDIM);
    const float var  = S2 * (1.0f / CDIM) - mean * mean;
    const float rs   = rsqrtf(var + LN_EPS);
#pragma unroll
    for (int j = 0; j < 4; j++) {
        const int c = t + j * 256;
        ctx[(size_t)row * CDIM + c] = (v[j] - mean) * rs * g[c] + b[c];
    }
}

// ---------------- host-side GEMM dispatch ----------------
static void run_gemm(int act, const float* A, const float* B, const float* bias,
                     float* C, int M, int N, int K)
{
    dim3 grid(N / BN, M / BM), block(256);
    switch (act) {
    case 0:
        cudaFuncSetAttribute(gemm3_kernel<0>, cudaFuncAttributeMaxDynamicSharedMemorySize, SMEM_BYTES);
        gemm3_kernel<0><<<grid, block, SMEM_BYTES>>>(A, B, bias, C, M, N, K);
        break;
    case 1:
        cudaFuncSetAttribute(gemm3_kernel<1>, cudaFuncAttributeMaxDynamicSharedMemorySize, SMEM_BYTES);
        gemm3_kernel<1><<<grid, block, SMEM_BYTES>>>(A, B, bias, C, M, N, K);
        break;
    case 2:
        cudaFuncSetAttribute(gemm3_kernel<2>, cudaFuncAttributeMaxDynamicSharedMemorySize, SMEM_BYTES);
        gemm3_kernel<2><<<grid, block, SMEM_BYTES>>>(A, B, bias, C, M, N, K);
        break;
    default:
        cudaFuncSetAttribute(gemm3_kernel<3>, cudaFuncAttributeMaxDynamicSharedMemorySize, SMEM_BYTES);
        gemm3_kernel<3><<<grid, block, SMEM_BYTES>>>(A, B, bias, C, M, N, K);
        break;
    }
}

extern "C" void kernel_launch(void* const* d_in, const int* in_sizes, int n_in,
                              void* d_out, int out_size)
{
    const int*   ids   = (const int*)d_in[0];
    const float* table = (const float*)d_in[1];
    const float* en_g  = (const float*)d_in[2];
    const float* en_b  = (const float*)d_in[3];
    const float* wA[2] = {(const float*)d_in[4],  (const float*)d_in[8]};
    const float* bA[2] = {(const float*)d_in[5],  (const float*)d_in[9]};
    const float* wB[2] = {(const float*)d_in[6],  (const float*)d_in[10]};
    const float* bB[2] = {(const float*)d_in[7],  (const float*)d_in[11]};
    const float* dw[2] = {(const float*)d_in[12], (const float*)d_in[20]};
    const float* db[2] = {(const float*)d_in[13], (const float*)d_in[21]};
    const float* fw[2] = {(const float*)d_in[14], (const float*)d_in[22]};
    const float* fb[2] = {(const float*)d_in[15], (const float*)d_in[23]};
    const float* iw[2] = {(const float*)d_in[16], (const float*)d_in[24]};
    const float* ib[2] = {(const float*)d_in[17], (const float*)d_in[25]};
    const float* cg[2] = {(const float*)d_in[18], (const float*)d_in[26]};
    const float* cb[2] = {(const float*)d_in[19], (const float*)d_in[27]};
    const float* ow    = (const float*)d_in[28];
    const float* ob    = (const float*)d_in[29];
    float* out = (float*)d_out;

    float *x, *xc, *h1, *h, *dd, *ff, *ii, *ctx;
    cudaGetSymbolAddress((void**)&x,   g_x);
    cudaGetSymbolAddress((void**)&xc,  g_xc);
    cudaGetSymbolAddress((void**)&h1,  g_h1);
    cudaGetSymbolAddress((void**)&h,   g_h);
    cudaGetSymbolAddress((void**)&dd,  g_del);
    cudaGetSymbolAddress((void**)&ff,  g_fg);
    cudaGetSymbolAddress((void**)&ii,  g_ig);
    cudaGetSymbolAddress((void**)&ctx, g_ctx);

    embed_ln_kernel<<<NTOK, 256>>>(ids, table, en_g, en_b, x);

    for (int blk = 0; blk < 2; ++blk) {
        const int first = (blk == 0) ? 1 : 0;
        concat_kernel<<<(NTOK * (EDIM + CDIM) / 4) / 256, 256>>>(x, ctx, xc, first);
        run_gemm(1, xc, wA[blk], bA[blk], h1, NTOK, HDIM, EDIM + CDIM);  // relu
        run_gemm(1, h1, wB[blk], bB[blk], h,  NTOK, HDIM, HDIM);         // relu
        run_gemm(2, h,  dw[blk], db[blk], dd, NTOK, CDIM, HDIM);         // tanh
        run_gemm(3, h,  fw[blk], fb[blk], ff, NTOK, CDIM, HDIM);         // sigmoid
        run_gemm(3, h,  iw[blk], ib[blk], ii, NTOK, CDIM, HDIM);         // sigmoid
        gate_ln_kernel<<<NTOK, 256>>>(ff, ii, dd, ctx, cg[blk], cb[blk], first);
    }

    run_gemm(0, h, ow, ob, out, NTOK, VDIM, HDIM);  // logits
}